// round 10
// baseline (speedup 1.0000x reference)
#include <cuda_runtime.h>
#include <cuda_fp16.h>

#define BB 4
#define NN 4096
#define DD 16
#define CC 128
#define LOG2E 1.4426950408889634f
#define NT 32

typedef unsigned long long ull;

__device__ __align__(16) float g_Q[BB * NN * DD];
__device__ __align__(16) float g_K[BB * NN * DD];   // pre-scaled by log2(e)
__device__ __align__(16) float g_V[BB * NN * DD];
__device__ __align__(16) __half g_E[(size_t)NN * NN];  // exp(e), ONE batch, [m][n]
__device__ float g_rowpart[4 * NN];                 // m-quarter partial row sums
__device__ float g_rowinv[NN];
__device__ float g_colinv[NN];
__device__ __align__(16) float g_xrpart[4 * NN * DD];  // m-quarter partial AV
__device__ float g_T[BB * DD * NN];
__device__ float g_part[BB * NT * 8];

__device__ __forceinline__ ull pack2(float lo, float hi) {
    ull r; asm("mov.b64 %0, {%1, %2};" : "=l"(r) : "f"(lo), "f"(hi)); return r;
}
__device__ __forceinline__ void unpack2(ull v, float& lo, float& hi) {
    asm("mov.b64 {%0, %1}, %2;" : "=f"(lo), "=f"(hi) : "l"(v));
}
__device__ __forceinline__ ull fma2(ull a, ull b, ull c) {
    ull d; asm("fma.rn.f32x2 %0, %1, %2, %3;" : "=l"(d) : "l"(a), "l"(b), "l"(c)); return d;
}
__device__ __forceinline__ ull add2(ull a, ull b) {
    ull d; asm("add.rn.f32x2 %0, %1, %2;" : "=l"(d) : "l"(a), "l"(b)); return d;
}
__device__ __forceinline__ float ex2(float x) {
    float y; asm("ex2.approx.ftz.f32 %0, %1;" : "=f"(y) : "f"(x)); return y;
}
__device__ __forceinline__ void cpa16(unsigned dst, const void* src) {
    asm volatile("cp.async.ca.shared.global [%0], [%1], 16;" :: "r"(dst), "l"(src));
}
__device__ __forceinline__ void cp_commit() { asm volatile("cp.async.commit_group;"); }
template <int N> __device__ __forceinline__ void cp_wait() {
    asm volatile("cp.async.wait_group %0;" :: "n"(N));
}

__device__ __forceinline__ float dotrr(const ull* q, const ull* kk) {
    ull a0 = fma2(q[0], kk[0], 0ULL);
    ull a1 = fma2(q[1], kk[1], 0ULL);
    ull a2 = fma2(q[2], kk[2], 0ULL);
    ull a3 = fma2(q[3], kk[3], 0ULL);
    a0 = fma2(q[4], kk[4], a0);
    a1 = fma2(q[5], kk[5], a1);
    a2 = fma2(q[6], kk[6], a2);
    a3 = fma2(q[7], kk[7], a3);
    ull s = add2(add2(a0, a1), add2(a2, a3));
    float x, y; unpack2(s, x, y);
    return x + y;
}

__device__ __forceinline__ void load_rows4(ull* dst, const float* base) {
    const ulonglong2* p = (const ulonglong2*)base;
#pragma unroll
    for (int r = 0; r < 4; r++)
#pragma unroll
        for (int i = 0; i < 4; i++) {
            ulonglong2 t = p[r * 4 + i];
            dst[r * 8 + 2 * i] = t.x; dst[r * 8 + 2 * i + 1] = t.y;
        }
}
__device__ __forceinline__ void ldk(ull* kk, const float* p) {
    const ulonglong2* k2 = (const ulonglong2*)p;
#pragma unroll
    for (int i = 0; i < 4; i++) { ulonglong2 t = k2[i]; kk[2 * i] = t.x; kk[2 * i + 1] = t.y; }
}

// ---------------------------------------------------------------------------
// Kernel 1: projections, ALL batches upfront (full grid).
// ---------------------------------------------------------------------------
__global__ void proj_kernel(const float* __restrict__ x_q, const float* __restrict__ x_kv,
                            const float* __restrict__ xyz_q, const float* __restrict__ xyz_kv,
                            const float* __restrict__ w_qk, const float* __restrict__ w_v,
                            const float* __restrict__ b_v,
                            const float* __restrict__ w_pos_q, const float* __restrict__ w_pos_kv) {
    __shared__ __align__(16) float s_wqk[CC][DD];
    __shared__ __align__(16) float s_wv[CC][DD];
    const int b = blockIdx.z;
    const int isKV = blockIdx.y;
    const int n = blockIdx.x * 128 + threadIdx.x;
    for (int i = threadIdx.x; i < CC * DD; i += 128) {
        int d = i / CC, c = i % CC;
        s_wqk[c][d] = w_qk[i];
        s_wv[c][d] = w_v[i];
    }
    __syncthreads();
    if (isKV == 0) {
        float p0 = xyz_q[(b * 3 + 0) * NN + n];
        float p1 = xyz_q[(b * 3 + 1) * NN + n];
        float p2 = xyz_q[(b * 3 + 2) * NN + n];
        float acc[DD];
#pragma unroll
        for (int d = 0; d < DD; d++)
            acc[d] = w_pos_q[d * 3] * p0 + w_pos_q[d * 3 + 1] * p1 + w_pos_q[d * 3 + 2] * p2;
        const float* xp = x_q + (size_t)b * CC * NN + n;
#pragma unroll 4
        for (int c = 0; c < CC; c++) {
            float xv = xp[(size_t)c * NN];
            const float4* w4 = (const float4*)s_wqk[c];
#pragma unroll
            for (int i = 0; i < 4; i++) {
                float4 w = w4[i];
                acc[4 * i + 0] += w.x * xv; acc[4 * i + 1] += w.y * xv;
                acc[4 * i + 2] += w.z * xv; acc[4 * i + 3] += w.w * xv;
            }
        }
        float4* qp = (float4*)(g_Q + ((size_t)(b * NN + n)) * DD);
#pragma unroll
        for (int i = 0; i < 4; i++)
            qp[i] = make_float4(acc[4 * i], acc[4 * i + 1], acc[4 * i + 2], acc[4 * i + 3]);
    } else {
        float p0 = xyz_kv[(b * 3 + 0) * NN + n];
        float p1 = xyz_kv[(b * 3 + 1) * NN + n];
        float p2 = xyz_kv[(b * 3 + 2) * NN + n];
        float ak[DD], av[DD];
#pragma unroll
        for (int d = 0; d < DD; d++) {
            float pos = w_pos_kv[d * 3] * p0 + w_pos_kv[d * 3 + 1] * p1 + w_pos_kv[d * 3 + 2] * p2;
            ak[d] = pos;
            av[d] = pos + b_v[d];
        }
        const float* xp = x_kv + (size_t)b * CC * NN + n;
#pragma unroll 2
        for (int c = 0; c < CC; c++) {
            float xv = xp[(size_t)c * NN];
            const float4* wq4 = (const float4*)s_wqk[c];
            const float4* wv4 = (const float4*)s_wv[c];
#pragma unroll
            for (int i = 0; i < 4; i++) {
                float4 wq = wq4[i], wv = wv4[i];
                ak[4 * i + 0] += wq.x * xv; ak[4 * i + 1] += wq.y * xv;
                ak[4 * i + 2] += wq.z * xv; ak[4 * i + 3] += wq.w * xv;
                av[4 * i + 0] += wv.x * xv; av[4 * i + 1] += wv.y * xv;
                av[4 * i + 2] += wv.z * xv; av[4 * i + 3] += wv.w * xv;
            }
        }
        float4* kp = (float4*)(g_K + ((size_t)(b * NN + n)) * DD);
        float4* vp = (float4*)(g_V + ((size_t)(b * NN + n)) * DD);
#pragma unroll
        for (int i = 0; i < 4; i++) {
            kp[i] = make_float4(ak[4 * i] * LOG2E, ak[4 * i + 1] * LOG2E,
                                ak[4 * i + 2] * LOG2E, ak[4 * i + 3] * LOG2E);
            vp[i] = make_float4(av[4 * i], av[4 * i + 1], av[4 * i + 2], av[4 * i + 3]);
        }
    }
}

// ---------------------------------------------------------------------------
// Kernel 2: rowsum (one batch, m-quarter per blockIdx.y) + store exp(e) fp16.
// 128 rows/block, 4 rows/lane, 8 warps; warp m-range 128 (4 tiles of 32).
// ---------------------------------------------------------------------------
__global__ __launch_bounds__(256, 1) void rowsum_kernel(int b) {
    __shared__ __align__(16) float sk[8][2][32 * DD];
    __shared__ float sred[8][128];
    const int tid = threadIdx.x, lane = tid & 31, w = tid >> 5;
    const int q = blockIdx.y;
    const int n0blk = blockIdx.x * 128;
    const int row0 = n0blk + lane * 4;
    const int m0 = q * 1024 + w * 128;

    ull qr[32];
    load_rows4(qr, g_Q + ((size_t)(b * NN + row0)) * DD);

    const char* kbase = (const char*)(g_K + ((size_t)b * NN + (size_t)m0) * DD);
    __half* ebase = g_E + (size_t)m0 * NN + n0blk + lane * 4;
    unsigned sb[2] = {(unsigned)__cvta_generic_to_shared(&sk[w][0][0]),
                      (unsigned)__cvta_generic_to_shared(&sk[w][1][0])};

#pragma unroll
    for (int j = 0; j < 4; j++)
        cpa16(sb[0] + (lane + j * 32) * 16, kbase + (lane + j * 32) * 16);
    cp_commit();

    float sum[4] = {0.f, 0.f, 0.f, 0.f};
    for (int it = 0; it < 4; ++it) {
        __syncwarp();
        if (it + 1 < 4) {
            const char* src = kbase + (size_t)(it + 1) * 2048;
            unsigned d = sb[(it + 1) & 1];
#pragma unroll
            for (int j = 0; j < 4; j++)
                cpa16(d + (lane + j * 32) * 16, src + (lane + j * 32) * 16);
            cp_commit();
            cp_wait<1>();
        } else {
            cp_wait<0>();
        }
        __syncwarp();
        const float* ks = &sk[w][it & 1][0];
        __half* ep = ebase + (size_t)(it * 32) * NN;
#pragma unroll 4
        for (int mm = 0; mm < 32; ++mm) {
            ull kk[8];
            ldk(kk, ks + mm * DD);
            float e0 = ex2(dotrr(qr, kk));
            float e1 = ex2(dotrr(qr + 8, kk));
            float e2 = ex2(dotrr(qr + 16, kk));
            float e3 = ex2(dotrr(qr + 24, kk));
            sum[0] += e0; sum[1] += e1; sum[2] += e2; sum[3] += e3;
            union { __half2 h[2]; ull u; } cv;
            cv.h[0] = __floats2half2_rn(e0, e1);
            cv.h[1] = __floats2half2_rn(e2, e3);
            *(ull*)(ep + (size_t)mm * NN) = cv.u;
        }
    }
#pragma unroll
    for (int r = 0; r < 4; r++) sred[w][lane * 4 + r] = sum[r];
    __syncthreads();
    if (tid < 128) {
        float tot = 0.f;
#pragma unroll
        for (int j = 0; j < 8; j++) tot += sred[j][tid];
        g_rowpart[q * NN + n0blk + tid] = tot;
    }
}

// ---------------------------------------------------------------------------
// Kernel 2b: fold 4 m-quarter partials into rowinv.
// ---------------------------------------------------------------------------
__global__ void rowfold_kernel() {
    int n = blockIdx.x * 256 + threadIdx.x;
    g_rowinv[n] = 1.0f / (g_rowpart[n] + g_rowpart[NN + n] +
                          g_rowpart[2 * NN + n] + g_rowpart[3 * NN + n]);
}

// ---------------------------------------------------------------------------
// Kernel 3: colsum (one batch). E rows come from L2. Warp per m.
// ---------------------------------------------------------------------------
__global__ __launch_bounds__(256, 1) void colsum_kernel() {
    __shared__ __align__(16) float sri[NN];
    const int tid = threadIdx.x, lane = tid & 31, w = tid >> 5;
    const int m = blockIdx.x * 8 + w;
    {
        const float4* src = (const float4*)g_rowinv;
        float4* dst = (float4*)sri;
        for (int i = tid; i < NN / 4; i += 256) dst[i] = src[i];
    }
    __syncthreads();
    const __half* ep = g_E + (size_t)m * NN;
    float s0 = 0.f, s1 = 0.f;
#pragma unroll
    for (int c = 0; c < 8; c++) {
        int n = c * 512 + lane * 16;
        uint4 ra = *(const uint4*)(ep + n);
        uint4 rb = *(const uint4*)(ep + n + 8);
        const __half2* ha = (const __half2*)&ra;
        const __half2* hb = (const __half2*)&rb;
        const float4* rp = (const float4*)(sri + n);
        float4 p0 = rp[0], p1 = rp[1], p2 = rp[2], p3 = rp[3];
        float2 f;
        f = __half22float2(ha[0]); s0 += f.x * p0.x + f.y * p0.y;
        f = __half22float2(ha[1]); s1 += f.x * p0.z + f.y * p0.w;
        f = __half22float2(ha[2]); s0 += f.x * p1.x + f.y * p1.y;
        f = __half22float2(ha[3]); s1 += f.x * p1.z + f.y * p1.w;
        f = __half22float2(hb[0]); s0 += f.x * p2.x + f.y * p2.y;
        f = __half22float2(hb[1]); s1 += f.x * p2.z + f.y * p2.w;
        f = __half22float2(hb[2]); s0 += f.x * p3.x + f.y * p3.y;
        f = __half22float2(hb[3]); s1 += f.x * p3.z + f.y * p3.w;
    }
    float s = s0 + s1;
#pragma unroll
    for (int o = 16; o > 0; o >>= 1) s += __shfl_xor_sync(0xffffffffu, s, o);
    if (lane == 0) g_colinv[m] = 1.0f / (1e-9f + s);
}

// ---------------------------------------------------------------------------
// Kernel 4a: AV partial sweep (one batch, m-quarter per blockIdx.y).
// E register double-buffer, V+colinv cp.async. Writes raw partial xr.
// ---------------------------------------------------------------------------
__global__ __launch_bounds__(256, 1) void pass3a_kernel(int b) {
    __shared__ __align__(16) float sbig[8192];
    __shared__ __align__(16) float sci[8][2][16];
    const int tid = threadIdx.x, lane = tid & 31, w = tid >> 5;
    const int q = blockIdx.y;
    const int n0blk = blockIdx.x * 128;
    const int m0 = q * 1024 + w * 128;

    const char* vbase = (const char*)(g_V + ((size_t)b * NN + (size_t)m0) * DD);
    const char* cibase = (const char*)(g_colinv + m0);
    const __half* ebase = g_E + (size_t)m0 * NN + n0blk + lane * 4;
    float* svw = sbig + w * 512;
    unsigned vb[2] = {(unsigned)__cvta_generic_to_shared(svw),
                      (unsigned)__cvta_generic_to_shared(svw + 256)};
    unsigned cb[2] = {(unsigned)__cvta_generic_to_shared(&sci[w][0][0]),
                      (unsigned)__cvta_generic_to_shared(&sci[w][1][0])};

    ull xr[32];
#pragma unroll
    for (int i = 0; i < 32; i++) xr[i] = 0ULL;

    auto issue = [&](int it, int buf) {
        const char* vsrc = vbase + (size_t)it * 1024;
        cpa16(vb[buf] + lane * 16, vsrc + lane * 16);
        cpa16(vb[buf] + 512 + lane * 16, vsrc + 512 + lane * 16);
        if (lane < 4) cpa16(cb[buf] + lane * 16, cibase + (size_t)it * 64 + lane * 16);
        cp_commit();
    };
    auto ld_eh = [&](ull* eh, int it) {
        const __half* ep = ebase + (size_t)(it * 16) * NN;
#pragma unroll
        for (int j = 0; j < 16; j++) eh[j] = *(const ull*)(ep + (size_t)j * NN);
    };
    auto compute = [&](const ull* eh, int buf) {
        const float* vs = svw + buf * 256;
        const float* ci = &sci[w][buf][0];
#pragma unroll
        for (int mm = 0; mm < 16; ++mm) {
            const __half2* hp = (const __half2*)&eh[mm];
            float2 wa = __half22float2(hp[0]);
            float2 wb = __half22float2(hp[1]);
            float c0 = ci[mm];
            wa.x *= c0; wa.y *= c0; wb.x *= c0; wb.y *= c0;
            ull vv[8];
            ldk(vv, vs + mm * DD);
            ull w0 = pack2(wa.x, wa.x), w1 = pack2(wa.y, wa.y);
            ull w2 = pack2(wb.x, wb.x), w3 = pack2(wb.y, wb.y);
#pragma unroll
            for (int i = 0; i < 8; i++) {
                xr[i]      = fma2(w0, vv[i], xr[i]);
                xr[8 + i]  = fma2(w1, vv[i], xr[8 + i]);
                xr[16 + i] = fma2(w2, vv[i], xr[16 + i]);
                xr[24 + i] = fma2(w3, vv[i], xr[24 + i]);
            }
        }
    };

    ull ehA[16], ehB[16];
    issue(0, 0);
    issue(1, 1);
    ld_eh(ehA, 0);
    cp_wait<1>();
    __syncwarp();

#pragma unroll 1
    for (int it = 0; it < 8; it += 2) {
        ld_eh(ehB, it + 1);
        compute(ehA, 0);
        __syncwarp();
        if (it + 2 < 8) { issue(it + 2, 0); cp_wait<1>(); } else { cp_wait<0>(); }
        __syncwarp();
        if (it + 2 < 8) ld_eh(ehA, it + 2);
        compute(ehB, 1);
        __syncwarp();
        if (it + 3 < 8) { issue(it + 3, 1); cp_wait<1>(); } else { cp_wait<0>(); }
        __syncwarp();
    }

    // reduce xr across 8 warps: 4 slots x 128 rows x 16 floats in sbig
    __syncthreads();
    if (w >= 4) {
        ull* d = (ull*)(sbig + ((size_t)(w - 4) * 128 + lane * 4) * DD);
#pragma unroll
        for (int i = 0; i < 32; i++) d[i] = xr[i];
    }
    __syncthreads();
    if (w < 4) {
        ull* d = (ull*)(sbig + ((size_t)w * 128 + lane * 4) * DD);
#pragma unroll
        for (int i = 0; i < 32; i++) d[i] = add2(d[i], xr[i]);
    }
    __syncthreads();

    if (tid < 128) {
        const int row = n0blk + tid;
        const float* s0 = sbig + tid * DD;
        float4* dst = (float4*)(g_xrpart + ((size_t)q * NN + row) * DD);
#pragma unroll
        for (int i = 0; i < 4; i++) {
            float a = s0[4 * i]     + s0[2048 + 4 * i]     + s0[4096 + 4 * i]     + s0[6144 + 4 * i];
            float c = s0[4 * i + 1] + s0[2048 + 4 * i + 1] + s0[4096 + 4 * i + 1] + s0[6144 + 4 * i + 1];
            float e = s0[4 * i + 2] + s0[2048 + 4 * i + 2] + s0[4096 + 4 * i + 2] + s0[6144 + 4 * i + 2];
            float g = s0[4 * i + 3] + s0[2048 + 4 * i + 3] + s0[4096 + 4 * i + 3] + s0[6144 + 4 * i + 3];
            dst[i] = make_float4(a, c, e, g);
        }
    }
}

// ---------------------------------------------------------------------------
// Kernel 4b: fold AV partials + w_t transform + GN partial stats (one batch).
// ---------------------------------------------------------------------------
__global__ __launch_bounds__(256, 1) void pass3b_kernel(const float* __restrict__ w_t,
                                                        const float* __restrict__ b_t, int b) {
    __shared__ float swt[256];
    __shared__ float sred[1024];
    const int tid = threadIdx.x;
    const int n0blk = blockIdx.x * 128;

    swt[tid] = w_t[tid];
    __syncthreads();

    if (tid < 128) {
        const int row = n0blk + tid;
        float rinv = g_rowinv[row];
        const float* x0 = g_xrpart + (size_t)row * DD;
        const float* x1 = x0 + (size_t)NN * DD;
        const float* x2 = x1 + (size_t)NN * DD;
        const float* x3 = x2 + (size_t)NN * DD;
        const float* qg = g_Q + ((size_t)(b * NN + row)) * DD;
        float diff[DD];
#pragma unroll
        for (int d = 0; d < DD; d++)
            diff[d] = qg[d] - (x0[d] + x1[d] + x2[d] + x3[d]) * rinv;
        float gs[4] = {0.f, 0.f, 0.f, 0.f}, gs2[4] = {0.f, 0.f, 0.f, 0.f};
#pragma unroll
        for (int o = 0; o < DD; o++) {
            float s = b_t[o];
#pragma unroll
            for (int d = 0; d < DD; d++) s += swt[o * DD + d] * diff[d];
            g_T[((size_t)(b * DD + o)) * NN + row] = s;
            gs[o >> 2] += s;
            gs2[o >> 2] += s * s;
        }
#pragma unroll
        for (int g = 0; g < 4; g++) {
            sred[tid * 8 + g] = gs[g];
            sred[tid * 8 + 4 + g] = gs2[g];
        }
    }
    __syncthreads();
    for (int s = 64; s > 0; s >>= 1) {
        if (tid < s) {
#pragma unroll
            for (int j = 0; j < 8; j++) sred[tid * 8 + j] += sred[(tid + s) * 8 + j];
        }
        __syncthreads();
    }
    if (tid < 8) g_part[((size_t)(b * NT + blockIdx.x)) * 8 + tid] = sred[tid];
}

// ---------------------------------------------------------------------------
// Kernel 5: finalize GN stats, relu, + q^T (all batches).
// ---------------------------------------------------------------------------
__global__ void final_kernel(const float* __restrict__ gamma, const float* __restrict__ beta,
                             float* __restrict__ out) {
    __shared__ float sq[128 * 17];
    __shared__ float ssc[DD], ssh[DD];
    const int b = blockIdx.y;
    const int tid = threadIdx.x;
    const int n0 = blockIdx.x * 128;
    if (tid < DD) {
        int g = tid >> 2;
        float s = 0.f, s2 = 0.f;
        for (int t = 0; t < NT; t++) {
            s += g_part[(b * NT + t) * 8 + g];
            s2 += g_part[(b * NT + t) * 8 + 4 + g];
        }
        float cnt = (float)(4 * NN);
        float mean = s / cnt;
        float var = s2 / cnt - mean * mean;
        float inv = rsqrtf(var + 1e-5f);
        float sc = gamma[tid] * inv;
        ssc[tid] = sc;
        ssh[tid] = beta[tid] - mean * sc;
    }
    const float* qsrc = g_Q + ((size_t)(b * NN + n0)) * DD;
    for (int i = tid; i < 128 * DD; i += 256) sq[(i >> 4) * 17 + (i & 15)] = qsrc[i];
    __syncthreads();
    for (int i = tid; i < 128 * DD; i += 256) {
        int c = i >> 7, j = i & 127;
        size_t idx = ((size_t)(b * DD + c)) * NN + n0 + j;
        float tv = g_T[idx];
        float r = fmaxf(tv * ssc[c] + ssh[c], 0.f);
        out[idx] = r + sq[j * 17 + c];
    }
}

extern "C" void kernel_launch(void* const* d_in, const int* in_sizes, int n_in,
                              void* d_out, int out_size) {
    const float* x_q      = (const float*)d_in[0];
    const float* x_kv     = (const float*)d_in[1];
    const float* xyz_q    = (const float*)d_in[2];
    const float* xyz_kv   = (const float*)d_in[3];
    const float* w_qk     = (const float*)d_in[4];
    const float* w_v      = (const float*)d_in[5];
    const float* b_v      = (const float*)d_in[6];
    const float* w_t      = (const float*)d_in[7];
    const float* b_t      = (const float*)d_in[8];
    const float* gamma    = (const float*)d_in[9];
    const float* beta     = (const float*)d_in[10];
    const float* w_pos_q  = (const float*)d_in[11];
    const float* w_pos_kv = (const float*)d_in[12];
    float* out = (float*)d_out;

    proj_kernel<<<dim3(32, 2, BB), 128>>>(x_q, x_kv, xyz_q, xyz_kv, w_qk, w_v, b_v,
                                          w_pos_q, w_pos_kv);
    for (int b = 0; b < BB; b++) {
        rowsum_kernel<<<dim3(32, 4), 256>>>(b);
        rowfold_kernel<<<16, 256>>>();
        colsum_kernel<<<512, 256>>>();
        pass3a_kernel<<<dim3(32, 4), 256>>>(b);
        pass3b_kernel<<<32, 256>>>(w_t, b_t, b);
    }
    final_kernel<<<dim3(32, BB), 256>>>(gamma, beta, out);
}

// round 11
// speedup vs baseline: 1.1348x; 1.1348x over previous
#include <cuda_runtime.h>
#include <cuda_fp16.h>

#define BB 4
#define NN 4096
#define DD 16
#define CC 128
#define LOG2E 1.4426950408889634f
#define NT 32

typedef unsigned long long ull;

__device__ __align__(16) float g_Q[BB * NN * DD];
__device__ __align__(16) float g_K[BB * NN * DD];   // pre-scaled by log2(e)
__device__ __align__(16) float g_V[BB * NN * DD];   // after colsum: u = colinv * v
__device__ __align__(16) __half g_E[(size_t)BB * NN * NN];  // exp(e), [b][m][n]
__device__ float g_rowinv[BB * NN];
__device__ float g_T[BB * DD * NN];
__device__ float g_part[BB * NT * 8];

__device__ __forceinline__ ull pack2(float lo, float hi) {
    ull r; asm("mov.b64 %0, {%1, %2};" : "=l"(r) : "f"(lo), "f"(hi)); return r;
}
__device__ __forceinline__ void unpack2(ull v, float& lo, float& hi) {
    asm("mov.b64 {%0, %1}, %2;" : "=f"(lo), "=f"(hi) : "l"(v));
}
__device__ __forceinline__ ull fma2(ull a, ull b, ull c) {
    ull d; asm("fma.rn.f32x2 %0, %1, %2, %3;" : "=l"(d) : "l"(a), "l"(b), "l"(c)); return d;
}
__device__ __forceinline__ ull add2(ull a, ull b) {
    ull d; asm("add.rn.f32x2 %0, %1, %2;" : "=l"(d) : "l"(a), "l"(b)); return d;
}
__device__ __forceinline__ float ex2(float x) {
    float y; asm("ex2.approx.ftz.f32 %0, %1;" : "=f"(y) : "f"(x)); return y;
}
__device__ __forceinline__ void cpa16(unsigned dst, const void* src) {
    asm volatile("cp.async.ca.shared.global [%0], [%1], 16;" :: "r"(dst), "l"(src));
}
__device__ __forceinline__ void cp_commit() { asm volatile("cp.async.commit_group;"); }
template <int N> __device__ __forceinline__ void cp_wait() {
    asm volatile("cp.async.wait_group %0;" :: "n"(N));
}

__device__ __forceinline__ float dotrr(const ull* q, const ull* kk) {
    ull a0 = fma2(q[0], kk[0], 0ULL);
    ull a1 = fma2(q[1], kk[1], 0ULL);
    ull a2 = fma2(q[2], kk[2], 0ULL);
    ull a3 = fma2(q[3], kk[3], 0ULL);
    a0 = fma2(q[4], kk[4], a0);
    a1 = fma2(q[5], kk[5], a1);
    a2 = fma2(q[6], kk[6], a2);
    a3 = fma2(q[7], kk[7], a3);
    ull s = add2(add2(a0, a1), add2(a2, a3));
    float x, y; unpack2(s, x, y);
    return x + y;
}

__device__ __forceinline__ void load_rows4(ull* dst, const float* base) {
    const ulonglong2* p = (const ulonglong2*)base;
#pragma unroll
    for (int r = 0; r < 4; r++)
#pragma unroll
        for (int i = 0; i < 4; i++) {
            ulonglong2 t = p[r * 4 + i];
            dst[r * 8 + 2 * i] = t.x; dst[r * 8 + 2 * i + 1] = t.y;
        }
}
__device__ __forceinline__ void ldk(ull* kk, const float* p) {
    const ulonglong2* k2 = (const ulonglong2*)p;
#pragma unroll
    for (int i = 0; i < 4; i++) { ulonglong2 t = k2[i]; kk[2 * i] = t.x; kk[2 * i + 1] = t.y; }
}

// ---------------------------------------------------------------------------
// Kernel 1: projections (R6). Q raw; K scaled by log2(e); V = wv@x + b_v + pos.
// ---------------------------------------------------------------------------
__global__ void proj_kernel(const float* __restrict__ x_q, const float* __restrict__ x_kv,
                            const float* __restrict__ xyz_q, const float* __restrict__ xyz_kv,
                            const float* __restrict__ w_qk, const float* __restrict__ w_v,
                            const float* __restrict__ b_v,
                            const float* __restrict__ w_pos_q, const float* __restrict__ w_pos_kv) {
    __shared__ __align__(16) float s_wqk[CC][DD];
    __shared__ __align__(16) float s_wv[CC][DD];
    const int b = blockIdx.z;
    const int isKV = blockIdx.y;
    const int n = blockIdx.x * 128 + threadIdx.x;
    for (int i = threadIdx.x; i < CC * DD; i += 128) {
        int d = i / CC, c = i % CC;
        s_wqk[c][d] = w_qk[i];
        s_wv[c][d] = w_v[i];
    }
    __syncthreads();
    if (isKV == 0) {
        float p0 = xyz_q[(b * 3 + 0) * NN + n];
        float p1 = xyz_q[(b * 3 + 1) * NN + n];
        float p2 = xyz_q[(b * 3 + 2) * NN + n];
        float acc[DD];
#pragma unroll
        for (int d = 0; d < DD; d++)
            acc[d] = w_pos_q[d * 3] * p0 + w_pos_q[d * 3 + 1] * p1 + w_pos_q[d * 3 + 2] * p2;
        const float* xp = x_q + (size_t)b * CC * NN + n;
#pragma unroll 4
        for (int c = 0; c < CC; c++) {
            float xv = xp[(size_t)c * NN];
            const float4* w4 = (const float4*)s_wqk[c];
#pragma unroll
            for (int i = 0; i < 4; i++) {
                float4 w = w4[i];
                acc[4 * i + 0] += w.x * xv; acc[4 * i + 1] += w.y * xv;
                acc[4 * i + 2] += w.z * xv; acc[4 * i + 3] += w.w * xv;
            }
        }
        float4* qp = (float4*)(g_Q + ((size_t)(b * NN + n)) * DD);
#pragma unroll
        for (int i = 0; i < 4; i++)
            qp[i] = make_float4(acc[4 * i], acc[4 * i + 1], acc[4 * i + 2], acc[4 * i + 3]);
    } else {
        float p0 = xyz_kv[(b * 3 + 0) * NN + n];
        float p1 = xyz_kv[(b * 3 + 1) * NN + n];
        float p2 = xyz_kv[(b * 3 + 2) * NN + n];
        float ak[DD], av[DD];
#pragma unroll
        for (int d = 0; d < DD; d++) {
            float pos = w_pos_kv[d * 3] * p0 + w_pos_kv[d * 3 + 1] * p1 + w_pos_kv[d * 3 + 2] * p2;
            ak[d] = pos;
            av[d] = pos + b_v[d];
        }
        const float* xp = x_kv + (size_t)b * CC * NN + n;
#pragma unroll 2
        for (int c = 0; c < CC; c++) {
            float xv = xp[(size_t)c * NN];
            const float4* wq4 = (const float4*)s_wqk[c];
            const float4* wv4 = (const float4*)s_wv[c];
#pragma unroll
            for (int i = 0; i < 4; i++) {
                float4 wq = wq4[i], wv = wv4[i];
                ak[4 * i + 0] += wq.x * xv; ak[4 * i + 1] += wq.y * xv;
                ak[4 * i + 2] += wq.z * xv; ak[4 * i + 3] += wq.w * xv;
                av[4 * i + 0] += wv.x * xv; av[4 * i + 1] += wv.y * xv;
                av[4 * i + 2] += wv.z * xv; av[4 * i + 3] += wv.w * xv;
            }
        }
        float4* kp = (float4*)(g_K + ((size_t)(b * NN + n)) * DD);
        float4* vp = (float4*)(g_V + ((size_t)(b * NN + n)) * DD);
#pragma unroll
        for (int i = 0; i < 4; i++) {
            kp[i] = make_float4(ak[4 * i] * LOG2E, ak[4 * i + 1] * LOG2E,
                                ak[4 * i + 2] * LOG2E, ak[4 * i + 3] * LOG2E);
            vp[i] = make_float4(av[4 * i], av[4 * i + 1], av[4 * i + 2], av[4 * i + 3]);
        }
    }
}

// ---------------------------------------------------------------------------
// Kernel 2 (R6): rowsum + store exp(e) fp16.
// ---------------------------------------------------------------------------
__global__ __launch_bounds__(256, 1) void rowsum_kernel() {
    __shared__ __align__(16) float sk[8][2][32 * DD];
    __shared__ float sred[8][128];
    const int tid = threadIdx.x, lane = tid & 31, w = tid >> 5;
    const int b = blockIdx.y;
    const int n0blk = blockIdx.x * 128;
    const int row0 = n0blk + lane * 4;

    ull qr[32];
    load_rows4(qr, g_Q + ((size_t)(b * NN + row0)) * DD);

    const char* kbase = (const char*)(g_K + ((size_t)b * NN + (size_t)w * 512) * DD);
    __half* ebase = g_E + ((size_t)(b * NN + w * 512)) * NN + n0blk + lane * 4;
    unsigned sb[2] = {(unsigned)__cvta_generic_to_shared(&sk[w][0][0]),
                      (unsigned)__cvta_generic_to_shared(&sk[w][1][0])};

#pragma unroll
    for (int j = 0; j < 4; j++)
        cpa16(sb[0] + (lane + j * 32) * 16, kbase + (lane + j * 32) * 16);
    cp_commit();

    float sum[4] = {0.f, 0.f, 0.f, 0.f};
    for (int it = 0; it < 16; ++it) {
        __syncwarp();
        if (it + 1 < 16) {
            const char* src = kbase + (size_t)(it + 1) * 2048;
            unsigned d = sb[(it + 1) & 1];
#pragma unroll
            for (int j = 0; j < 4; j++)
                cpa16(d + (lane + j * 32) * 16, src + (lane + j * 32) * 16);
            cp_commit();
            cp_wait<1>();
        } else {
            cp_wait<0>();
        }
        __syncwarp();
        const float* ks = &sk[w][it & 1][0];
        __half* ep = ebase + (size_t)(it * 32) * NN;
#pragma unroll 4
        for (int mm = 0; mm < 32; ++mm) {
            ull kk[8];
            ldk(kk, ks + mm * DD);
            float e0 = ex2(dotrr(qr, kk));
            float e1 = ex2(dotrr(qr + 8, kk));
            float e2 = ex2(dotrr(qr + 16, kk));
            float e3 = ex2(dotrr(qr + 24, kk));
            sum[0] += e0; sum[1] += e1; sum[2] += e2; sum[3] += e3;
            union { __half2 h[2]; ull u; } cv;
            cv.h[0] = __floats2half2_rn(e0, e1);
            cv.h[1] = __floats2half2_rn(e2, e3);
            *(ull*)(ep + (size_t)mm * NN) = cv.u;
        }
    }
#pragma unroll
    for (int r = 0; r < 4; r++) sred[w][lane * 4 + r] = sum[r];
    __syncthreads();
    if (tid < 128) {
        float tot = 0.f;
#pragma unroll
        for (int j = 0; j < 8; j++) tot += sred[j][tid];
        g_rowinv[b * NN + n0blk + tid] = 1.0f / tot;
    }
}

// ---------------------------------------------------------------------------
// Kernel 3: colsum, MLP-restructured. Warp per m. Per half-row: 8 front-batched
// LDG.128s into registers, then consume. Epilogue folds colinv into V in place.
// ---------------------------------------------------------------------------
__global__ __launch_bounds__(256, 2) void colsum_kernel() {
    __shared__ __align__(16) float sri[NN];
    const int tid = threadIdx.x, lane = tid & 31, w = tid >> 5;
    const int b = blockIdx.y;
    const int m = blockIdx.x * 8 + w;
    {
        const float4* src = (const float4*)(g_rowinv + b * NN);
        float4* dst = (float4*)sri;
        for (int i = tid; i < NN / 4; i += 256) dst[i] = src[i];
    }
    __syncthreads();
    const __half* ep = g_E + ((size_t)(b * NN + m)) * NN;
    float s0 = 0.f, s1 = 0.f;
#pragma unroll
    for (int h = 0; h < 2; h++) {
        uint4 raw[8];
#pragma unroll
        for (int c = 0; c < 4; c++) {
            int n = (h * 4 + c) * 512 + lane * 16;
            raw[2 * c] = *(const uint4*)(ep + n);
            raw[2 * c + 1] = *(const uint4*)(ep + n + 8);
        }
#pragma unroll
        for (int c = 0; c < 4; c++) {
            int n = (h * 4 + c) * 512 + lane * 16;
            const __half2* ha = (const __half2*)&raw[2 * c];
            const __half2* hb = (const __half2*)&raw[2 * c + 1];
            const float4* rp = (const float4*)(sri + n);
            float4 p0 = rp[0], p1 = rp[1], p2 = rp[2], p3 = rp[3];
            float2 f;
            f = __half22float2(ha[0]); s0 += f.x * p0.x + f.y * p0.y;
            f = __half22float2(ha[1]); s1 += f.x * p0.z + f.y * p0.w;
            f = __half22float2(ha[2]); s0 += f.x * p1.x + f.y * p1.y;
            f = __half22float2(ha[3]); s1 += f.x * p1.z + f.y * p1.w;
            f = __half22float2(hb[0]); s0 += f.x * p2.x + f.y * p2.y;
            f = __half22float2(hb[1]); s1 += f.x * p2.z + f.y * p2.w;
            f = __half22float2(hb[2]); s0 += f.x * p3.x + f.y * p3.y;
            f = __half22float2(hb[3]); s1 += f.x * p3.z + f.y * p3.w;
        }
    }
    float s = s0 + s1;
#pragma unroll
    for (int o = 16; o > 0; o >>= 1) s += __shfl_xor_sync(0xffffffffu, s, o);
    // fold colinv into V in place: u = ci * v  (all 16 lanes write one float)
    float ci = 1.0f / (1e-9f + s);
    if (lane < DD) {
        float* vp = g_V + ((size_t)(b * NN + m)) * DD + lane;
        *vp = *vp * ci;
    }
}

// ---------------------------------------------------------------------------
// Kernel 4 (R6, simplified): AV sweep. E in register double-buffer, u (=ci*v)
// via cp.async double-buffer. No colinv stream.
// ---------------------------------------------------------------------------
__global__ __launch_bounds__(256, 1) void pass3_kernel(const float* __restrict__ w_t,
                                                       const float* __restrict__ b_t) {
    __shared__ __align__(16) float sbig[8192];
    __shared__ float swt[256];
    __shared__ float sred[1024];
    const int tid = threadIdx.x, lane = tid & 31, w = tid >> 5;
    const int b = blockIdx.y;
    const int n0blk = blockIdx.x * 128;

    swt[tid] = w_t[tid];

    const char* vbase = (const char*)(g_V + ((size_t)b * NN + (size_t)w * 512) * DD);
    const __half* ebase = g_E + ((size_t)(b * NN + w * 512)) * NN + n0blk + lane * 4;
    float* svw = sbig + w * 512;
    unsigned vb[2] = {(unsigned)__cvta_generic_to_shared(svw),
                      (unsigned)__cvta_generic_to_shared(svw + 256)};

    ull xr[32];
#pragma unroll
    for (int i = 0; i < 32; i++) xr[i] = 0ULL;

    auto issue = [&](int it, int buf) {
        const char* vsrc = vbase + (size_t)it * 1024;
        cpa16(vb[buf] + lane * 16, vsrc + lane * 16);
        cpa16(vb[buf] + 512 + lane * 16, vsrc + 512 + lane * 16);
        cp_commit();
    };
    auto ld_eh = [&](ull* eh, int it) {
        const __half* ep = ebase + (size_t)(it * 16) * NN;
#pragma unroll
        for (int j = 0; j < 16; j++) eh[j] = *(const ull*)(ep + (size_t)j * NN);
    };
    auto compute = [&](const ull* eh, int buf) {
        const float* vs = svw + buf * 256;
#pragma unroll
        for (int mm = 0; mm < 16; ++mm) {
            const __half2* hp = (const __half2*)&eh[mm];
            float2 wa = __half22float2(hp[0]);
            float2 wb = __half22float2(hp[1]);
            ull vv[8];
            ldk(vv, vs + mm * DD);
            ull w0 = pack2(wa.x, wa.x), w1 = pack2(wa.y, wa.y);
            ull w2 = pack2(wb.x, wb.x), w3 = pack2(wb.y, wb.y);
#pragma unroll
            for (int i = 0; i < 8; i++) {
                xr[i]      = fma2(w0, vv[i], xr[i]);
                xr[8 + i]  = fma2(w1, vv[i], xr[8 + i]);
                xr[16 + i] = fma2(w2, vv[i], xr[16 + i]);
                xr[24 + i] = fma2(w3, vv[i], xr[24 + i]);
            }
        }
    };

    ull ehA[16], ehB[16];
    issue(0, 0);
    issue(1, 1);
    ld_eh(ehA, 0);
    cp_wait<1>();
    __syncwarp();

#pragma unroll 1
    for (int it = 0; it < 32; it += 2) {
        ld_eh(ehB, it + 1);
        compute(ehA, 0);
        __syncwarp();
        if (it + 2 < 32) { issue(it + 2, 0); cp_wait<1>(); } else { cp_wait<0>(); }
        __syncwarp();
        if (it + 2 < 32) ld_eh(ehA, it + 2);
        compute(ehB, 1);
        __syncwarp();
        if (it + 3 < 32) { issue(it + 3, 1); cp_wait<1>(); } else { cp_wait<0>(); }
        __syncwarp();
    }

    __syncthreads();
    if (w >= 4) {
        ull* d = (ull*)(sbig + ((size_t)(w - 4) * 128 + lane * 4) * DD);
#pragma unroll
        for (int i = 0; i < 32; i++) d[i] = xr[i];
    }
    __syncthreads();
    if (w < 4) {
        ull* d = (ull*)(sbig + ((size_t)w * 128 + lane * 4) * DD);
#pragma unroll
        for (int i = 0; i < 32; i++) d[i] = add2(d[i], xr[i]);
    }
    __syncthreads();

    if (tid < 128) {
        const int row = n0blk + tid;
        float rinv = g_rowinv[b * NN + row];
        float xrf[DD];
        const float* s0 = sbig + tid * DD;
#pragma unroll
        for (int d = 0; d < DD; d++)
            xrf[d] = (s0[d] + s0[2048 + d] + s0[4096 + d] + s0[6144 + d]) * rinv;
        const float* qg = g_Q + ((size_t)(b * NN + row)) * DD;
        float diff[DD];
#pragma unroll
        for (int d = 0; d < DD; d++) diff[d] = qg[d] - xrf[d];
        float gs[4] = {0.f, 0.f, 0.f, 0.f}, gs2[4] = {0.f, 0.f, 0.f, 0.f};
#pragma unroll
        for (int o = 0; o < DD; o++) {
            float s = b_t[o];
#pragma unroll
            for (int d = 0; d < DD; d++) s += swt[o * DD + d] * diff[d];
            g_T[((size_t)(b * DD + o)) * NN + row] = s;
            gs[o >> 2] += s;
            gs2[o >> 2] += s * s;
        }
#pragma unroll
        for (int g = 0; g < 4; g++) {
            sred[tid * 8 + g] = gs[g];
            sred[tid * 8 + 4 + g] = gs2[g];
        }
    }
    __syncthreads();
    for (int s = 64; s > 0; s >>= 1) {
        if (tid < s) {
#pragma unroll
            for (int j = 0; j < 8; j++) sred[tid * 8 + j] += sred[(tid + s) * 8 + j];
        }
        __syncthreads();
    }
    if (tid < 8) g_part[((size_t)(b * NT + blockIdx.x)) * 8 + tid] = sred[tid];
}

// ---------------------------------------------------------------------------
// Kernel 5 (R6): finalize GN stats, relu, + q^T.
// ---------------------------------------------------------------------------
__global__ void final_kernel(const float* __restrict__ gamma, const float* __restrict__ beta,
                             float* __restrict__ out) {
    __shared__ float sq[128 * 17];
    __shared__ float ssc[DD], ssh[DD];
    const int b = blockIdx.y;
    const int tid = threadIdx.x;
    const int n0 = blockIdx.x * 128;
    if (tid < DD) {
        int g = tid >> 2;
        float s = 0.f, s2 = 0.f;
        for (int t = 0; t < NT; t++) {
            s += g_part[(b * NT + t) * 8 + g];
            s2 += g_part[(b * NT + t) * 8 + 4 + g];
        }
        float cnt = (float)(4 * NN);
        float mean = s / cnt;
        float var = s2 / cnt - mean * mean;
        float inv = rsqrtf(var + 1e-5f);
        float sc = gamma[tid] * inv;
        ssc[tid] = sc;
        ssh[tid] = beta[tid] - mean * sc;
    }
    const float* qsrc = g_Q + ((size_t)(b * NN + n0)) * DD;
    for (int i = tid; i < 128 * DD; i += 256) sq[(i >> 4) * 17 + (i & 15)] = qsrc[i];
    __syncthreads();
    for (int i = tid; i < 128 * DD; i += 256) {
        int c = i >> 7, j = i & 127;
        size_t idx = ((size_t)(b * DD + c)) * NN + n0 + j;
        float tv = g_T[idx];
        float r = fmaxf(tv * ssc[c] + ssh[c], 0.f);
        out[idx] = r + sq[j * 17 + c];
    }
}

extern "C" void kernel_launch(void* const* d_in, const int* in_sizes, int n_in,
                              void* d_out, int out_size) {
    const float* x_q      = (const float*)d_in[0];
    const float* x_kv     = (const float*)d_in[1];
    const float* xyz_q    = (const float*)d_in[2];
    const float* xyz_kv   = (const float*)d_in[3];
    const float* w_qk     = (const float*)d_in[4];
    const float* w_v      = (const float*)d_in[5];
    const float* b_v      = (const float*)d_in[6];
    const float* w_t      = (const float*)d_in[7];
    const float* b_t      = (const float*)d_in[8];
    const float* gamma    = (const float*)d_in[9];
    const float* beta     = (const float*)d_in[10];
    const float* w_pos_q  = (const float*)d_in[11];
    const float* w_pos_kv = (const float*)d_in[12];
    float* out = (float*)d_out;

    proj_kernel<<<dim3(32, 2, BB), 128>>>(x_q, x_kv, xyz_q, xyz_kv, w_qk, w_v, b_v,
                                          w_pos_q, w_pos_kv);
    rowsum_kernel<<<dim3(32, BB), 256>>>();
    colsum_kernel<<<dim3(512, BB), 256>>>();
    pass3_kernel<<<dim3(NT, BB), 256>>>(w_t, b_t);
    final_kernel<<<dim3(32, BB), 256>>>(gamma, beta, out);
}